// round 1
// baseline (speedup 1.0000x reference)
#include <cuda_runtime.h>
#include <cuda_bf16.h>
#include <math.h>

// Problem constants
#define T_LEN 2048
#define NH    32
#define HKV   8
#define HD    128
#define INNER 4096      // NH*HD
#define KVI   1024      // HKV*HD

// Scratch (device globals: no allocation allowed)
__device__ float g_q[T_LEN * INNER];   // 33.5 MB
__device__ float g_k[T_LEN * KVI];     //  8.4 MB
__device__ float g_v[T_LEN * KVI];     //  8.4 MB
__device__ float g_ao[T_LEN * INNER];  // 33.5 MB

// ---------------------------------------------------------------------------
// C[M,N] = A[M,K] @ B[N,K]^T      (both row-major, K contiguous)
// 128x128 block tile, BK=8, 256 threads, 8x8 per thread.
// Thread (tr,tc): rows tr*8..+7, cols {tc*4..+3, 64+tc*4..+3} (split for LDS)
// ---------------------------------------------------------------------------
__global__ __launch_bounds__(256) void gemm_nt_kernel(
    const float* __restrict__ A, const float* __restrict__ B,
    float* __restrict__ C, int M, int N, int K)
{
    __shared__ float As[8][128];
    __shared__ float Bs[8][128];

    const int tid = threadIdx.x;
    const int tr  = tid >> 4;         // 0..15
    const int tc  = tid & 15;         // 0..15
    const int row0 = blockIdx.y * 128;
    const int col0 = blockIdx.x * 128;

    const int lr = tid >> 1;          // 0..127
    const int lc = (tid & 1) * 4;     // 0 or 4

    const float* Ap = A + (size_t)(row0 + lr) * K + lc;
    const float* Bp = B + (size_t)(col0 + lr) * K + lc;

    float acc[8][8];
#pragma unroll
    for (int i = 0; i < 8; i++)
#pragma unroll
        for (int j = 0; j < 8; j++) acc[i][j] = 0.f;

    for (int k0 = 0; k0 < K; k0 += 8) {
        float4 a4 = *(const float4*)(Ap + k0);
        float4 b4 = *(const float4*)(Bp + k0);
        As[lc + 0][lr] = a4.x; As[lc + 1][lr] = a4.y;
        As[lc + 2][lr] = a4.z; As[lc + 3][lr] = a4.w;
        Bs[lc + 0][lr] = b4.x; Bs[lc + 1][lr] = b4.y;
        Bs[lc + 2][lr] = b4.z; Bs[lc + 3][lr] = b4.w;
        __syncthreads();
#pragma unroll
        for (int kk = 0; kk < 8; kk++) {
            float a[8], b[8];
            *(float4*)&a[0] = *(const float4*)&As[kk][tr * 8];
            *(float4*)&a[4] = *(const float4*)&As[kk][tr * 8 + 4];
            *(float4*)&b[0] = *(const float4*)&Bs[kk][tc * 4];
            *(float4*)&b[4] = *(const float4*)&Bs[kk][64 + tc * 4];
#pragma unroll
            for (int i = 0; i < 8; i++)
#pragma unroll
                for (int j = 0; j < 8; j++)
                    acc[i][j] += a[i] * b[j];
        }
        __syncthreads();
    }

#pragma unroll
    for (int i = 0; i < 8; i++) {
        float4 c0 = make_float4(acc[i][0], acc[i][1], acc[i][2], acc[i][3]);
        float4 c1 = make_float4(acc[i][4], acc[i][5], acc[i][6], acc[i][7]);
        size_t r = (size_t)(row0 + tr * 8 + i) * N;
        *(float4*)(C + r + col0 + tc * 4) = c0;
        *(float4*)(C + r + col0 + 64 + tc * 4) = c1;
    }
}

// ---------------------------------------------------------------------------
// RoPE (NeoX rotate-half) applied in place to q (32 heads) and k (8 heads).
// One block per position t. invf[d] = 10000^(-d/64).
// ---------------------------------------------------------------------------
__global__ __launch_bounds__(256) void rope_kernel(float* __restrict__ q,
                                                   float* __restrict__ k)
{
    __shared__ float sInv[64];
    const int t = blockIdx.x;
    if (threadIdx.x < 64)
        sInv[threadIdx.x] =
            (float)exp2(-(double)threadIdx.x * 0.20762050593045952); // log2(1e4)/64
    __syncthreads();

    for (int p = threadIdx.x; p < (NH + HKV) * 64; p += 256) {
        float* base;
        int d;
        if (p < NH * 64) {
            base = q + (size_t)t * INNER + (p >> 6) * HD;
            d = p & 63;
        } else {
            int pp = p - NH * 64;
            base = k + (size_t)t * KVI + (pp >> 6) * HD;
            d = pp & 63;
        }
        float ang = (float)t * sInv[d];
        float s, c;
        sincosf(ang, &s, &c);
        float x1 = base[d], x2 = base[d + 64];
        base[d]      = x1 * c - x2 * s;
        base[d + 64] = x2 * c + x1 * s;
    }
}

// ---------------------------------------------------------------------------
// Causal flash attention, fp32. Block = (64 q-rows, 1 head). 256 threads.
// Per k-tile (64 keys): S = Q K^T, online softmax, O += P V.
// K/V smem uses an XOR swizzle on 16B groups to keep LDS conflicts <= 2-way.
// Thread (tr,tc): S rows 4tr..+3 x cols 4tc..+3; O rows 4tr..+3,
// cols {tc*4..+3, 64+tc*4..+3}.
// ---------------------------------------------------------------------------
__global__ __launch_bounds__(256) void attn_kernel(
    const float* __restrict__ Q, const float* __restrict__ Kg,
    const float* __restrict__ Vg, float* __restrict__ O)
{
    extern __shared__ float sm[];
    float* sQ   = sm;            // 64*128
    float* sKV  = sm + 8192;     // 64*128, swizzled (K then reused for V)
    float* sP   = sm + 16384;    // 64*64
    float* sRed = sm + 20480;    // 64*17

    const int h   = blockIdx.y;
    const int qb  = blockIdx.x;
    const int hk  = h >> 2;
    const int q0  = qb * 64;
    const int tid = threadIdx.x;
    const int tr  = tid >> 4;
    const int tc  = tid & 15;

#pragma unroll
    for (int it = 0; it < 8; it++) {
        int idx = tid + it * 256;
        int row = idx >> 5, dg = idx & 31;
        *(float4*)(sQ + row * 128 + dg * 4) =
            *(const float4*)(Q + (size_t)(q0 + row) * INNER + h * HD + dg * 4);
    }

    float m_i[4], l_i[4], acc[4][8];
#pragma unroll
    for (int i = 0; i < 4; i++) {
        m_i[i] = -INFINITY;
        l_i[i] = 0.f;
#pragma unroll
        for (int j = 0; j < 8; j++) acc[i][j] = 0.f;
    }
    const float scale = 0.08838834764831845f; // 1/sqrt(128)

    for (int kt = 0; kt <= qb; kt++) {
        const int k0 = kt * 64;
        __syncthreads();  // sQ ready (1st iter) / prev tile finished with sKV & sP

        // K tile -> sKV (swizzled)
#pragma unroll
        for (int it = 0; it < 8; it++) {
            int idx = tid + it * 256;
            int row = idx >> 5, dg = idx & 31;
            int slot = dg ^ ((row >> 2) & 7);
            *(float4*)(sKV + row * 128 + slot * 4) =
                *(const float4*)(Kg + (size_t)(k0 + row) * KVI + hk * HD + dg * 4);
        }
        __syncthreads();

        // S = Q K^T (4x4 per thread)
        float s[4][4];
#pragma unroll
        for (int i = 0; i < 4; i++)
#pragma unroll
            for (int j = 0; j < 4; j++) s[i][j] = 0.f;

#pragma unroll 4
        for (int dg = 0; dg < 32; dg++) {
            float4 q4[4], k4[4];
            int slot = (dg ^ (tc & 7)) * 4;
#pragma unroll
            for (int i = 0; i < 4; i++)
                q4[i] = *(const float4*)(sQ + (4 * tr + i) * 128 + dg * 4);
#pragma unroll
            for (int j = 0; j < 4; j++)
                k4[j] = *(const float4*)(sKV + (4 * tc + j) * 128 + slot);
#pragma unroll
            for (int i = 0; i < 4; i++)
#pragma unroll
                for (int j = 0; j < 4; j++)
                    s[i][j] += q4[i].x * k4[j].x + q4[i].y * k4[j].y +
                               q4[i].z * k4[j].z + q4[i].w * k4[j].w;
        }

        // scale + causal mask (only the diagonal tile needs masking)
        if (kt == qb) {
#pragma unroll
            for (int i = 0; i < 4; i++)
#pragma unroll
                for (int j = 0; j < 4; j++)
                    s[i][j] = (k0 + 4 * tc + j > q0 + 4 * tr + i)
                                  ? -1e30f : s[i][j] * scale;
        } else {
#pragma unroll
            for (int i = 0; i < 4; i++)
#pragma unroll
                for (int j = 0; j < 4; j++) s[i][j] *= scale;
        }

        // partial row max
#pragma unroll
        for (int i = 0; i < 4; i++) {
            float mx = fmaxf(fmaxf(s[i][0], s[i][1]), fmaxf(s[i][2], s[i][3]));
            sRed[(4 * tr + i) * 17 + tc] = mx;
        }
        __syncthreads();  // all S-reads of sKV done -> safe to overwrite with V

        // V tile -> sKV (overlaps the max reduction)
#pragma unroll
        for (int it = 0; it < 8; it++) {
            int idx = tid + it * 256;
            int row = idx >> 5, dg = idx & 31;
            int slot = dg ^ ((row >> 2) & 7);
            *(float4*)(sKV + row * 128 + slot * 4) =
                *(const float4*)(Vg + (size_t)(k0 + row) * KVI + hk * HD + dg * 4);
        }

        float newm[4];
#pragma unroll
        for (int i = 0; i < 4; i++) {
            float mx = m_i[i];
            const float* rr = sRed + (4 * tr + i) * 17;
#pragma unroll
            for (int t2 = 0; t2 < 16; t2++) mx = fmaxf(mx, rr[t2]);
            newm[i] = mx;
        }
        __syncthreads();  // sRed consumed; V writes landed

        // P = exp(S - m'), partial row sums, stage P in smem
#pragma unroll
        for (int i = 0; i < 4; i++) {
            float su = 0.f;
#pragma unroll
            for (int j = 0; j < 4; j++) {
                float p = __expf(s[i][j] - newm[i]);
                sP[(4 * tr + i) * 64 + 4 * tc + j] = p;
                su += p;
            }
            sRed[(4 * tr + i) * 17 + tc] = su;
        }
        __syncthreads();

#pragma unroll
        for (int i = 0; i < 4; i++) {
            float su = 0.f;
            const float* rr = sRed + (4 * tr + i) * 17;
#pragma unroll
            for (int t2 = 0; t2 < 16; t2++) su += rr[t2];
            float corr = __expf(m_i[i] - newm[i]);
            l_i[i] = l_i[i] * corr + su;
            m_i[i] = newm[i];
#pragma unroll
            for (int j = 0; j < 8; j++) acc[i][j] *= corr;
        }

        // O += P @ V
#pragma unroll 2
        for (int kk = 0; kk < 64; kk++) {
            int sl = (kk >> 2) & 7;
            int sa = tc ^ sl;
            float4 va = *(const float4*)(sKV + kk * 128 + sa * 4);
            float4 vb = *(const float4*)(sKV + kk * 128 + (sa + 16) * 4);
#pragma unroll
            for (int i = 0; i < 4; i++) {
                float p = sP[(4 * tr + i) * 64 + kk];
                acc[i][0] += p * va.x; acc[i][1] += p * va.y;
                acc[i][2] += p * va.z; acc[i][3] += p * va.w;
                acc[i][4] += p * vb.x; acc[i][5] += p * vb.y;
                acc[i][6] += p * vb.z; acc[i][7] += p * vb.w;
            }
        }
    }

#pragma unroll
    for (int i = 0; i < 4; i++) {
        float inv = 1.f / l_i[i];
        float4 c0 = make_float4(acc[i][0] * inv, acc[i][1] * inv,
                                acc[i][2] * inv, acc[i][3] * inv);
        float4 c1 = make_float4(acc[i][4] * inv, acc[i][5] * inv,
                                acc[i][6] * inv, acc[i][7] * inv);
        size_t base = (size_t)(q0 + 4 * tr + i) * INNER + h * HD;
        *(float4*)(O + base + tc * 4) = c0;
        *(float4*)(O + base + 64 + tc * 4) = c1;
    }
}

// ---------------------------------------------------------------------------
extern "C" void kernel_launch(void* const* d_in, const int* in_sizes, int n_in,
                              void* d_out, int out_size)
{
    (void)in_sizes; (void)n_in; (void)out_size;
    const float* stm = (const float*)d_in[0];
    const float* w_q = (const float*)d_in[1];
    const float* w_k = (const float*)d_in[2];
    const float* w_v = (const float*)d_in[3];
    const float* w_o = (const float*)d_in[4];
    float* out = (float*)d_out;

    float *pq, *pk, *pv, *pa;
    cudaGetSymbolAddress((void**)&pq, g_q);
    cudaGetSymbolAddress((void**)&pk, g_k);
    cudaGetSymbolAddress((void**)&pv, g_v);
    cudaGetSymbolAddress((void**)&pa, g_ao);

    const int attn_smem = (8192 + 8192 + 4096 + 64 * 17) * 4; // 86272 B
    cudaFuncSetAttribute(attn_kernel,
                         cudaFuncAttributeMaxDynamicSharedMemorySize, attn_smem);

    dim3 gq(INNER / 128, T_LEN / 128);  // (32,16)
    dim3 gk(KVI / 128, T_LEN / 128);    // (8,16)

    gemm_nt_kernel<<<gq, 256>>>(stm, w_q, pq, T_LEN, INNER, INNER);
    gemm_nt_kernel<<<gk, 256>>>(stm, w_k, pk, T_LEN, KVI, INNER);
    gemm_nt_kernel<<<gk, 256>>>(stm, w_v, pv, T_LEN, KVI, INNER);

    rope_kernel<<<T_LEN, 256>>>(pq, pk);

    attn_kernel<<<dim3(T_LEN / 64, NH), 256, attn_smem>>>(pq, pk, pv, pa);

    gemm_nt_kernel<<<gq, 256>>>(pa, w_o, out, T_LEN, INNER, INNER);
}

// round 3
// speedup vs baseline: 2.1193x; 2.1193x over previous
#include <cuda_runtime.h>
#include <cuda_bf16.h>
#include <math.h>
#include <cstdint>
#include <cstddef>

// Problem constants
#define T_LEN 2048
#define NH    32
#define HKV   8
#define HD    128
#define INNER 4096      // NH*HD
#define KVI   1024      // HKV*HD

// tcgen05 is an arch-accelerated feature: it only exists in the compute_103a
// pass. The harness also builds a plain compute_103 PTX pass for JIT
// fallback; the guards below stub the tcgen05 asm there so ptxas accepts it.
// The driver always picks the exact sm_103a cubin on GB300.
#if defined(__CUDA_ARCH_FEAT_SM103_ALL) || defined(__CUDA_ARCH_FEAT_SM100_ALL)
#define TC_OK 1
#else
#define TC_OK 0
#endif

// ---------------------------------------------------------------------------
// Scratch (device globals: no allocation allowed)
// ---------------------------------------------------------------------------
__device__ float g_q [T_LEN * INNER];
__device__ float g_k [T_LEN * KVI];
__device__ float g_v [T_LEN * KVI];
__device__ float g_ao[T_LEN * INNER];

__device__ __nv_bfloat16 g_xh [T_LEN * INNER], g_xl [T_LEN * INNER];
__device__ __nv_bfloat16 g_wqh[INNER * INNER], g_wql[INNER * INNER];
__device__ __nv_bfloat16 g_wkh[KVI  * INNER], g_wkl[KVI  * INNER];
__device__ __nv_bfloat16 g_wvh[KVI  * INNER], g_wvl[KVI  * INNER];
__device__ __nv_bfloat16 g_woh[INNER * INNER], g_wol[INNER * INNER];
__device__ __nv_bfloat16 g_aoh[T_LEN * INNER], g_aol[T_LEN * INNER];

// ---------------------------------------------------------------------------
// PTX helpers (sm_103a)
// ---------------------------------------------------------------------------
static __device__ __forceinline__ uint32_t s2u(const void* p) {
    uint32_t a;
    asm("{ .reg .u64 t; cvta.to.shared.u64 t, %1; cvt.u32.u64 %0, t; }"
        : "=r"(a) : "l"(p));
    return a;
}
static __device__ __forceinline__ uint32_t elect1() {
    uint32_t p;
    asm volatile("{ .reg .pred p; elect.sync _|p, 0xFFFFFFFF; selp.b32 %0,1,0,p; }"
                 : "=r"(p));
    return p;
}
static __device__ __forceinline__ void mbar_init(uint32_t a, uint32_t n) {
    asm volatile("mbarrier.init.shared.b64 [%0], %1;" :: "r"(a), "r"(n) : "memory");
}
static __device__ __forceinline__ void mbar_wait(uint32_t a, uint32_t par) {
    asm volatile(
        "{\n\t.reg .pred P;\n\t"
        "LAB%=:\n\t"
        "mbarrier.try_wait.parity.acquire.cta.shared::cta.b64 P, [%0], %1, 0x989680;\n\t"
        "@P bra DONE%=;\n\t"
        "bra LAB%=;\n\t"
        "DONE%=:\n\t}"
        :: "r"(a), "r"(par) : "memory");
}
static __device__ __forceinline__ void tc_alloc(uint32_t smem_addr, uint32_t ncols) {
#if TC_OK
    asm volatile("tcgen05.alloc.cta_group::1.sync.aligned.shared::cta.b32 [%0], %1;"
                 :: "r"(smem_addr), "r"(ncols) : "memory");
#endif
}
static __device__ __forceinline__ void tc_relinq() {
#if TC_OK
    asm volatile("tcgen05.relinquish_alloc_permit.cta_group::1.sync.aligned;");
#endif
}
static __device__ __forceinline__ void tc_dealloc(uint32_t tmem, uint32_t ncols) {
#if TC_OK
    asm volatile("tcgen05.dealloc.cta_group::1.sync.aligned.b32 %0, %1;"
                 :: "r"(tmem), "r"(ncols));
#endif
}
static __device__ __forceinline__ void tc_commit(uint32_t mbar) {
#if TC_OK
    asm volatile("tcgen05.commit.cta_group::1.mbarrier::arrive::one.shared::cluster.b64 [%0];"
                 :: "r"(mbar) : "memory");
#endif
}
static __device__ __forceinline__ void tc_mma_f16_ss(uint32_t d, uint64_t ad, uint64_t bd,
                                                     uint32_t idesc, uint32_t en) {
#if TC_OK
    asm volatile(
        "{\n\t.reg .pred p;\n\t"
        "setp.ne.u32 p, %4, 0;\n\t"
        "tcgen05.mma.cta_group::1.kind::f16 [%0], %1, %2, %3, {%5,%5,%5,%5}, p;\n\t}"
        :: "r"(d), "l"(ad), "l"(bd), "r"(idesc), "r"(en), "r"(0u) : "memory");
#endif
}
static __device__ __forceinline__ void tc_waitld() {
#if TC_OK
    asm volatile("tcgen05.wait::ld.sync.aligned;" ::: "memory");
#endif
}
static __device__ __forceinline__ void tc_fence_after() {
#if TC_OK
    asm volatile("tcgen05.fence::after_thread_sync;" ::: "memory");
#endif
}
static __device__ __forceinline__ void tc_fence_before() {
#if TC_OK
    asm volatile("tcgen05.fence::before_thread_sync;" ::: "memory");
#endif
}
static __device__ __forceinline__ void fence_async() {
    asm volatile("fence.proxy.async.shared::cta;" ::: "memory");
}
static __device__ __forceinline__ void tc_ld32(uint32_t* r, uint32_t ta) {
#if TC_OK
    asm volatile(
        "tcgen05.ld.sync.aligned.32x32b.x32.b32 "
        "{%0, %1, %2, %3, %4, %5, %6, %7, "
        " %8, %9, %10, %11, %12, %13, %14, %15, "
        " %16, %17, %18, %19, %20, %21, %22, %23, "
        " %24, %25, %26, %27, %28, %29, %30, %31}, [%32];"
        : "=r"(r[0]),  "=r"(r[1]),  "=r"(r[2]),  "=r"(r[3]),
          "=r"(r[4]),  "=r"(r[5]),  "=r"(r[6]),  "=r"(r[7]),
          "=r"(r[8]),  "=r"(r[9]),  "=r"(r[10]), "=r"(r[11]),
          "=r"(r[12]), "=r"(r[13]), "=r"(r[14]), "=r"(r[15]),
          "=r"(r[16]), "=r"(r[17]), "=r"(r[18]), "=r"(r[19]),
          "=r"(r[20]), "=r"(r[21]), "=r"(r[22]), "=r"(r[23]),
          "=r"(r[24]), "=r"(r[25]), "=r"(r[26]), "=r"(r[27]),
          "=r"(r[28]), "=r"(r[29]), "=r"(r[30]), "=r"(r[31])
        : "r"(ta));
#else
    for (int i = 0; i < 32; i++) r[i] = 0u;
    (void)ta;
#endif
}
static __device__ __forceinline__ uint64_t mk_desc(uint32_t addr) {
    // SW128, Blackwell version=1, LBO=1 (16B), SBO=64 (1024B per 8-row atom)
    const uint64_t BASE = (2ull << 61) | (1ull << 46) | (64ull << 32) | (1ull << 16);
    return BASE | ((uint64_t)(addr >> 4) & 0x3FFF);
}

// ---------------------------------------------------------------------------
// fp32 -> (bf16 hi, bf16 lo) split.  hi = rn(x), lo = rn(x - hi)
// ---------------------------------------------------------------------------
__global__ __launch_bounds__(256) void split_kernel(
    const float* __restrict__ in, __nv_bfloat16* __restrict__ hi,
    __nv_bfloat16* __restrict__ lo, int n)
{
    int stride = gridDim.x * blockDim.x * 4;
    for (int i = (blockIdx.x * blockDim.x + threadIdx.x) * 4; i < n; i += stride) {
        float4 x = *(const float4*)(in + i);
        __nv_bfloat16 h0 = __float2bfloat16(x.x);
        __nv_bfloat16 h1 = __float2bfloat16(x.y);
        __nv_bfloat16 h2 = __float2bfloat16(x.z);
        __nv_bfloat16 h3 = __float2bfloat16(x.w);
        __nv_bfloat16 l0 = __float2bfloat16(x.x - __bfloat162float(h0));
        __nv_bfloat16 l1 = __float2bfloat16(x.y - __bfloat162float(h1));
        __nv_bfloat16 l2 = __float2bfloat16(x.z - __bfloat162float(h2));
        __nv_bfloat16 l3 = __float2bfloat16(x.w - __bfloat162float(h3));
        __nv_bfloat162* hp = (__nv_bfloat162*)(hi + i);
        __nv_bfloat162* lp = (__nv_bfloat162*)(lo + i);
        hp[0] = __nv_bfloat162(h0, h1); hp[1] = __nv_bfloat162(h2, h3);
        lp[0] = __nv_bfloat162(l0, l1); lp[1] = __nv_bfloat162(l2, l3);
    }
}

// ---------------------------------------------------------------------------
// tcgen05 bf16x3 GEMM: C[M,N] = Ah@Bh^T + Ah@Bl^T + Al@Bh^T   (fp32 accum)
// A [M,K] K-major bf16, B [N,K] K-major bf16. 128x128 tile per CTA.
// K staged in chunks of 64 (128B SW128 rows), 3-stage pipeline, mbarrier
// ring guards smem reuse against in-flight MMA.
// ---------------------------------------------------------------------------
#define GSTAGES  3
#define GCHUNK   64
#define GTILE_B  16384
#define GSTAGE_B (4 * GTILE_B)          // 65536
#define GCTRL    (GSTAGES * GSTAGE_B)   // 196608
#define GSMEM    (GCTRL + 64)

__global__ __launch_bounds__(256) void gemm_tc_kernel(
    const __nv_bfloat16* __restrict__ Ah, const __nv_bfloat16* __restrict__ Al,
    const __nv_bfloat16* __restrict__ Bh, const __nv_bfloat16* __restrict__ Bl,
    float* __restrict__ C, int N, int K)
{
    extern __shared__ char sm_raw[];
    const uint32_t sb  = s2u(sm_raw);
    const int tid = threadIdx.x;
    const int wid = tid >> 5;
    const int m0  = blockIdx.y * 128;
    const int n0  = blockIdx.x * 128;

    if (wid == 0) { tc_alloc(sb + GCTRL + 32, 128); tc_relinq(); }
    if (tid == 0) {
        mbar_init(sb + GCTRL + 0, 1);
        mbar_init(sb + GCTRL + 8, 1);
        mbar_init(sb + GCTRL + 16, 1);
    }
    __syncthreads();
    uint32_t tmem;
    asm volatile("ld.shared.b32 %0, [%1];" : "=r"(tmem) : "r"(sb + GCTRL + 32));

    const uint32_t idesc = (1u << 4) | (1u << 7) | (1u << 10) |
                           ((128u / 8) << 17) | ((128u / 16) << 24);

    const int KW = K >> 3;              // uint4 per gmem row
    const int g  = tid & 7;             // 16B group within 128B row
    const int rb = tid >> 3;            // 0..31
    const int sc = g ^ (rb & 7);        // swizzled slot (constant per thread)
    const size_t a4 = (((size_t)(m0 + rb) * K) >> 3) + g;
    const size_t b4 = (((size_t)(n0 + rb) * K) >> 3) + g;

    int ph0 = 0, ph1 = 0, ph2 = 0;
    const int NCH = K / GCHUNK;

    for (int c = 0; c < NCH; c++) {
        const int s = c % 3;
        const uint32_t mb = sb + GCTRL + s * 8;
        if (c >= 3) {
            int p = (s == 0) ? ph0 : ((s == 1) ? ph1 : ph2);
            mbar_wait(mb, p);
            if (s == 0) ph0 ^= 1; else if (s == 1) ph1 ^= 1; else ph2 ^= 1;
        }

        const size_t ko4 = (size_t)c * 8;   // uint4 offset within row
        const uint4* srcs[4] = { (const uint4*)Ah, (const uint4*)Al,
                                 (const uint4*)Bh, (const uint4*)Bl };
#pragma unroll
        for (int t = 0; t < 4; t++) {
            const size_t base = ((t < 2) ? a4 : b4) + ko4;
            const uint4* sp = srcs[t];
            uint4* dp = (uint4*)(sm_raw + (size_t)s * GSTAGE_B + (size_t)t * GTILE_B);
            uint4 v0 = sp[base];
            uint4 v1 = sp[base + (size_t)32 * KW];
            uint4 v2 = sp[base + (size_t)64 * KW];
            uint4 v3 = sp[base + (size_t)96 * KW];
            dp[rb * 8 + sc]        = v0;
            dp[(rb + 32) * 8 + sc] = v1;
            dp[(rb + 64) * 8 + sc] = v2;
            dp[(rb + 96) * 8 + sc] = v3;
        }
        __syncthreads();

        if (wid == 0 && elect1()) {
            fence_async();
            const uint32_t sa = sb + s * GSTAGE_B;
            const uint64_t dAh = mk_desc(sa);
            const uint64_t dAl = mk_desc(sa + GTILE_B);
            const uint64_t dBh = mk_desc(sa + 2 * GTILE_B);
            const uint64_t dBl = mk_desc(sa + 3 * GTILE_B);
#pragma unroll
            for (int ks = 0; ks < 4; ks++)
                tc_mma_f16_ss(tmem, dAh + ks * 2, dBh + ks * 2, idesc,
                              (c == 0 && ks == 0) ? 0u : 1u);
#pragma unroll
            for (int ks = 0; ks < 4; ks++)
                tc_mma_f16_ss(tmem, dAh + ks * 2, dBl + ks * 2, idesc, 1u);
#pragma unroll
            for (int ks = 0; ks < 4; ks++)
                tc_mma_f16_ss(tmem, dAl + ks * 2, dBh + ks * 2, idesc, 1u);
            tc_commit(mb);
        }
    }

    // Final wait: last chunk's commit covers all prior MMA.
    {
        const int s = (NCH - 1) % 3;
        int p = (s == 0) ? ph0 : ((s == 1) ? ph1 : ph2);
        mbar_wait(sb + GCTRL + s * 8, p);
    }
    tc_fence_after();

    if (tid < 128) {
#pragma unroll
        for (int cb = 0; cb < 128; cb += 32) {
            uint32_t dr[32];
            tc_ld32(dr, tmem + cb);
            tc_waitld();
            float* cp = C + (size_t)(m0 + tid) * N + n0 + cb;
#pragma unroll
            for (int j = 0; j < 32; j += 4) {
                float4 v = make_float4(__uint_as_float(dr[j]),
                                       __uint_as_float(dr[j + 1]),
                                       __uint_as_float(dr[j + 2]),
                                       __uint_as_float(dr[j + 3]));
                *(float4*)(cp + j) = v;
            }
        }
        tc_fence_before();
    }
    __syncthreads();
    if (wid == 0) tc_dealloc(tmem, 128);
}

// ---------------------------------------------------------------------------
// RoPE (NeoX rotate-half) applied in place to q (32 heads) and k (8 heads).
// ---------------------------------------------------------------------------
__global__ __launch_bounds__(256) void rope_kernel(float* __restrict__ q,
                                                   float* __restrict__ k)
{
    __shared__ float sInv[64];
    const int t = blockIdx.x;
    if (threadIdx.x < 64)
        sInv[threadIdx.x] =
            (float)exp2(-(double)threadIdx.x * 0.20762050593045952); // log2(1e4)/64
    __syncthreads();

    for (int p = threadIdx.x; p < (NH + HKV) * 64; p += 256) {
        float* base;
        int d;
        if (p < NH * 64) {
            base = q + (size_t)t * INNER + (p >> 6) * HD;
            d = p & 63;
        } else {
            int pp = p - NH * 64;
            base = k + (size_t)t * KVI + (pp >> 6) * HD;
            d = pp & 63;
        }
        float ang = (float)t * sInv[d];
        float s, c;
        sincosf(ang, &s, &c);
        float x1 = base[d], x2 = base[d + 64];
        base[d]      = x1 * c - x2 * s;
        base[d + 64] = x2 * c + x1 * s;
    }
}

// ---------------------------------------------------------------------------
// Causal flash attention, fp32 (unchanged from round 1).
// ---------------------------------------------------------------------------
__global__ __launch_bounds__(256) void attn_kernel(
    const float* __restrict__ Q, const float* __restrict__ Kg,
    const float* __restrict__ Vg, float* __restrict__ O)
{
    extern __shared__ float sm[];
    float* sQ   = sm;            // 64*128
    float* sKV  = sm + 8192;     // 64*128, swizzled (K then reused for V)
    float* sP   = sm + 16384;    // 64*64
    float* sRed = sm + 20480;    // 64*17

    const int h   = blockIdx.y;
    const int qb  = blockIdx.x;
    const int hk  = h >> 2;
    const int q0  = qb * 64;
    const int tid = threadIdx.x;
    const int tr  = tid >> 4;
    const int tc  = tid & 15;

#pragma unroll
    for (int it = 0; it < 8; it++) {
        int idx = tid + it * 256;
        int row = idx >> 5, dg = idx & 31;
        *(float4*)(sQ + row * 128 + dg * 4) =
            *(const float4*)(Q + (size_t)(q0 + row) * INNER + h * HD + dg * 4);
    }

    float m_i[4], l_i[4], acc[4][8];
#pragma unroll
    for (int i = 0; i < 4; i++) {
        m_i[i] = -INFINITY;
        l_i[i] = 0.f;
#pragma unroll
        for (int j = 0; j < 8; j++) acc[i][j] = 0.f;
    }
    const float scale = 0.08838834764831845f;

    for (int kt = 0; kt <= qb; kt++) {
        const int k0 = kt * 64;
        __syncthreads();

#pragma unroll
        for (int it = 0; it < 8; it++) {
            int idx = tid + it * 256;
            int row = idx >> 5, dg = idx & 31;
            int slot = dg ^ ((row >> 2) & 7);
            *(float4*)(sKV + row * 128 + slot * 4) =
                *(const float4*)(Kg + (size_t)(k0 + row) * KVI + hk * HD + dg * 4);
        }
        __syncthreads();

        float s[4][4];
#pragma unroll
        for (int i = 0; i < 4; i++)
#pragma unroll
            for (int j = 0; j < 4; j++) s[i][j] = 0.f;

#pragma unroll 4
        for (int dg = 0; dg < 32; dg++) {
            float4 q4[4], k4[4];
            int slot = (dg ^ (tc & 7)) * 4;
#pragma unroll
            for (int i = 0; i < 4; i++)
                q4[i] = *(const float4*)(sQ + (4 * tr + i) * 128 + dg * 4);
#pragma unroll
            for (int j = 0; j < 4; j++)
                k4[j] = *(const float4*)(sKV + (4 * tc + j) * 128 + slot);
#pragma unroll
            for (int i = 0; i < 4; i++)
#pragma unroll
                for (int j = 0; j < 4; j++)
                    s[i][j] += q4[i].x * k4[j].x + q4[i].y * k4[j].y +
                               q4[i].z * k4[j].z + q4[i].w * k4[j].w;
        }

        if (kt == qb) {
#pragma unroll
            for (int i = 0; i < 4; i++)
#pragma unroll
                for (int j = 0; j < 4; j++)
                    s[i][j] = (k0 + 4 * tc + j > q0 + 4 * tr + i)
                                  ? -1e30f : s[i][j] * scale;
        } else {
#pragma unroll
            for (int i = 0; i < 4; i++)
#pragma unroll
                for (int j = 0; j < 4; j++) s[i][j] *= scale;
        }

#pragma unroll
        for (int i = 0; i < 4; i++) {
            float mx = fmaxf(fmaxf(s[i][0], s[i][1]), fmaxf(s[i][2], s[i][3]));
            sRed[(4 * tr + i) * 17 + tc] = mx;
        }
        __syncthreads();

#pragma unroll
        for (int it = 0; it < 8; it++) {
            int idx = tid + it * 256;
            int row = idx >> 5, dg = idx & 31;
            int slot = dg ^ ((row >> 2) & 7);
            *(float4*)(sKV + row * 128 + slot * 4) =
                *(const float4*)(Vg + (size_t)(k0 + row) * KVI + hk * HD + dg * 4);
        }

        float newm[4];
#pragma unroll
        for (int i = 0; i < 4; i++) {
            float mx = m_i[i];
            const float* rr = sRed + (4 * tr + i) * 17;
#pragma unroll
            for (int t2 = 0; t2 < 16; t2++) mx = fmaxf(mx, rr[t2]);
            newm[i] = mx;
        }
        __syncthreads();

#pragma unroll
        for (int i = 0; i < 4; i++) {
            float su = 0.f;
#pragma unroll
            for (int j = 0; j < 4; j++) {
                float p = __expf(s[i][j] - newm[i]);
                sP[(4 * tr + i) * 64 + 4 * tc + j] = p;
                su += p;
            }
            sRed[(4 * tr + i) * 17 + tc] = su;
        }
        __syncthreads();

#pragma unroll
        for (int i = 0; i < 4; i++) {
            float su = 0.f;
            const float* rr = sRed + (4 * tr + i) * 17;
#pragma unroll
            for (int t2 = 0; t2 < 16; t2++) su += rr[t2];
            float corr = __expf(m_i[i] - newm[i]);
            l_i[i] = l_i[i] * corr + su;
            m_i[i] = newm[i];
#pragma unroll
            for (int j = 0; j < 8; j++) acc[i][j] *= corr;
        }

#pragma unroll 2
        for (int kk = 0; kk < 64; kk++) {
            int sl = (kk >> 2) & 7;
            int sa = tc ^ sl;
            float4 va = *(const float4*)(sKV + kk * 128 + sa * 4);
            float4 vb = *(const float4*)(sKV + kk * 128 + (sa + 16) * 4);
#pragma unroll
            for (int i = 0; i < 4; i++) {
                float p = sP[(4 * tr + i) * 64 + kk];
                acc[i][0] += p * va.x; acc[i][1] += p * va.y;
                acc[i][2] += p * va.z; acc[i][3] += p * va.w;
                acc[i][4] += p * vb.x; acc[i][5] += p * vb.y;
                acc[i][6] += p * vb.z; acc[i][7] += p * vb.w;
            }
        }
    }

#pragma unroll
    for (int i = 0; i < 4; i++) {
        float inv = 1.f / l_i[i];
        float4 c0 = make_float4(acc[i][0] * inv, acc[i][1] * inv,
                                acc[i][2] * inv, acc[i][3] * inv);
        float4 c1 = make_float4(acc[i][4] * inv, acc[i][5] * inv,
                                acc[i][6] * inv, acc[i][7] * inv);
        size_t base = (size_t)(q0 + 4 * tr + i) * INNER + h * HD;
        *(float4*)(O + base + tc * 4) = c0;
        *(float4*)(O + base + 64 + tc * 4) = c1;
    }
}

// ---------------------------------------------------------------------------
extern "C" void kernel_launch(void* const* d_in, const int* in_sizes, int n_in,
                              void* d_out, int out_size)
{
    (void)in_sizes; (void)n_in; (void)out_size;
    const float* stm = (const float*)d_in[0];
    const float* w_q = (const float*)d_in[1];
    const float* w_k = (const float*)d_in[2];
    const float* w_v = (const float*)d_in[3];
    const float* w_o = (const float*)d_in[4];
    float* out = (float*)d_out;

    float *pq, *pk, *pv, *pa;
    cudaGetSymbolAddress((void**)&pq, g_q);
    cudaGetSymbolAddress((void**)&pk, g_k);
    cudaGetSymbolAddress((void**)&pv, g_v);
    cudaGetSymbolAddress((void**)&pa, g_ao);

    __nv_bfloat16 *xh, *xl, *wqh, *wql, *wkh, *wkl, *wvh, *wvl, *woh, *wol, *aoh, *aol;
    cudaGetSymbolAddress((void**)&xh,  g_xh);  cudaGetSymbolAddress((void**)&xl,  g_xl);
    cudaGetSymbolAddress((void**)&wqh, g_wqh); cudaGetSymbolAddress((void**)&wql, g_wql);
    cudaGetSymbolAddress((void**)&wkh, g_wkh); cudaGetSymbolAddress((void**)&wkl, g_wkl);
    cudaGetSymbolAddress((void**)&wvh, g_wvh); cudaGetSymbolAddress((void**)&wvl, g_wvl);
    cudaGetSymbolAddress((void**)&woh, g_woh); cudaGetSymbolAddress((void**)&wol, g_wol);
    cudaGetSymbolAddress((void**)&aoh, g_aoh); cudaGetSymbolAddress((void**)&aol, g_aol);

    const int attn_smem = (8192 + 8192 + 4096 + 64 * 17) * 4; // 86272 B
    cudaFuncSetAttribute(attn_kernel,
                         cudaFuncAttributeMaxDynamicSharedMemorySize, attn_smem);
    cudaFuncSetAttribute(gemm_tc_kernel,
                         cudaFuncAttributeMaxDynamicSharedMemorySize, GSMEM);

    // Splits
    split_kernel<<<4096, 256>>>(stm, xh,  xl,  T_LEN * INNER);
    split_kernel<<<4096, 256>>>(w_q, wqh, wql, INNER * INNER);
    split_kernel<<<4096, 256>>>(w_k, wkh, wkl, KVI * INNER);
    split_kernel<<<4096, 256>>>(w_v, wvh, wvl, KVI * INNER);
    split_kernel<<<4096, 256>>>(w_o, woh, wol, INNER * INNER);

    // Projections (tcgen05 bf16x3)
    gemm_tc_kernel<<<dim3(INNER / 128, T_LEN / 128), 256, GSMEM>>>(
        xh, xl, wqh, wql, pq, INNER, INNER);
    gemm_tc_kernel<<<dim3(KVI / 128, T_LEN / 128), 256, GSMEM>>>(
        xh, xl, wkh, wkl, pk, KVI, INNER);
    gemm_tc_kernel<<<dim3(KVI / 128, T_LEN / 128), 256, GSMEM>>>(
        xh, xl, wvh, wvl, pv, KVI, INNER);

    rope_kernel<<<T_LEN, 256>>>(pq, pk);

    attn_kernel<<<dim3(T_LEN / 64, NH), 256, attn_smem>>>(pq, pk, pv, pa);

    split_kernel<<<4096, 256>>>(pa, aoh, aol, T_LEN * INNER);
    gemm_tc_kernel<<<dim3(INNER / 128, T_LEN / 128), 256, GSMEM>>>(
        aoh, aol, woh, wol, out, INNER, INNER);
}

// round 6
// speedup vs baseline: 3.3363x; 1.5742x over previous
#include <cuda_runtime.h>
#include <cuda_bf16.h>
#include <math.h>
#include <cstdint>
#include <cstddef>

// Problem constants
#define T_LEN 2048
#define NH    32
#define HKV   8
#define HD    128
#define INNER 4096      // NH*HD
#define KVI   1024      // HKV*HD

// tcgen05 only exists in the compute_103a pass; the plain compute_103 JIT
// fallback pass compiles these as stubs (never executed on GB300).
#if defined(__CUDA_ARCH_FEAT_SM103_ALL) || defined(__CUDA_ARCH_FEAT_SM100_ALL)
#define TC_OK 1
#else
#define TC_OK 0
#endif

// ---------------------------------------------------------------------------
// Scratch (device globals: no allocation allowed)
// ---------------------------------------------------------------------------
__device__ float g_q [T_LEN * INNER];
__device__ float g_k [T_LEN * KVI];
__device__ float g_v [T_LEN * KVI];
__device__ float g_ao[T_LEN * INNER];

__device__ __nv_bfloat16 g_xh [T_LEN * INNER], g_xl [T_LEN * INNER];
__device__ __nv_bfloat16 g_wqh[INNER * INNER], g_wql[INNER * INNER];
__device__ __nv_bfloat16 g_wkh[KVI  * INNER], g_wkl[KVI  * INNER];
__device__ __nv_bfloat16 g_wvh[KVI  * INNER], g_wvl[KVI  * INNER];
__device__ __nv_bfloat16 g_woh[INNER * INNER], g_wol[INNER * INNER];
__device__ __nv_bfloat16 g_aoh[T_LEN * INNER], g_aol[T_LEN * INNER];

// ---------------------------------------------------------------------------
// PTX helpers (sm_103a)
// ---------------------------------------------------------------------------
static __device__ __forceinline__ uint32_t s2u(const void* p) {
    uint32_t a;
    asm("{ .reg .u64 t; cvta.to.shared.u64 t, %1; cvt.u32.u64 %0, t; }"
        : "=r"(a) : "l"(p));
    return a;
}
static __device__ __forceinline__ uint32_t elect1() {
    uint32_t p;
    asm volatile("{ .reg .pred p; elect.sync _|p, 0xFFFFFFFF; selp.b32 %0,1,0,p; }"
                 : "=r"(p));
    return p;
}
static __device__ __forceinline__ void mbar_init(uint32_t a, uint32_t n) {
    asm volatile("mbarrier.init.shared.b64 [%0], %1;" :: "r"(a), "r"(n) : "memory");
}
static __device__ __forceinline__ void mbar_wait(uint32_t a, uint32_t par) {
    asm volatile(
        "{\n\t.reg .pred P;\n\t"
        "LAB%=:\n\t"
        "mbarrier.try_wait.parity.acquire.cta.shared::cta.b64 P, [%0], %1, 0x989680;\n\t"
        "@P bra DONE%=;\n\t"
        "bra LAB%=;\n\t"
        "DONE%=:\n\t}"
        :: "r"(a), "r"(par) : "memory");
}
static __device__ __forceinline__ void tc_alloc(uint32_t smem_addr, uint32_t ncols) {
#if TC_OK
    asm volatile("tcgen05.alloc.cta_group::1.sync.aligned.shared::cta.b32 [%0], %1;"
                 :: "r"(smem_addr), "r"(ncols) : "memory");
#endif
}
static __device__ __forceinline__ void tc_relinq() {
#if TC_OK
    asm volatile("tcgen05.relinquish_alloc_permit.cta_group::1.sync.aligned;");
#endif
}
static __device__ __forceinline__ void tc_dealloc(uint32_t tmem, uint32_t ncols) {
#if TC_OK
    asm volatile("tcgen05.dealloc.cta_group::1.sync.aligned.b32 %0, %1;"
                 :: "r"(tmem), "r"(ncols));
#endif
}
static __device__ __forceinline__ void tc_commit(uint32_t mbar) {
#if TC_OK
    asm volatile("tcgen05.commit.cta_group::1.mbarrier::arrive::one.shared::cluster.b64 [%0];"
                 :: "r"(mbar) : "memory");
#endif
}
static __device__ __forceinline__ void tc_mma_f16_ss(uint32_t d, uint64_t ad, uint64_t bd,
                                                     uint32_t idesc, uint32_t en) {
#if TC_OK
    asm volatile(
        "{\n\t.reg .pred p;\n\t"
        "setp.ne.u32 p, %4, 0;\n\t"
        "tcgen05.mma.cta_group::1.kind::f16 [%0], %1, %2, %3, {%5,%5,%5,%5}, p;\n\t}"
        :: "r"(d), "l"(ad), "l"(bd), "r"(idesc), "r"(en), "r"(0u) : "memory");
#endif
}
static __device__ __forceinline__ void tc_waitld() {
#if TC_OK
    asm volatile("tcgen05.wait::ld.sync.aligned;" ::: "memory");
#endif
}
static __device__ __forceinline__ void tc_fence_after() {
#if TC_OK
    asm volatile("tcgen05.fence::after_thread_sync;" ::: "memory");
#endif
}
static __device__ __forceinline__ void tc_fence_before() {
#if TC_OK
    asm volatile("tcgen05.fence::before_thread_sync;" ::: "memory");
#endif
}
static __device__ __forceinline__ void fence_async() {
    asm volatile("fence.proxy.async.shared::cta;" ::: "memory");
}
static __device__ __forceinline__ void tc_ld32(uint32_t* r, uint32_t ta) {
#if TC_OK
    asm volatile(
        "tcgen05.ld.sync.aligned.32x32b.x32.b32 "
        "{%0, %1, %2, %3, %4, %5, %6, %7, "
        " %8, %9, %10, %11, %12, %13, %14, %15, "
        " %16, %17, %18, %19, %20, %21, %22, %23, "
        " %24, %25, %26, %27, %28, %29, %30, %31}, [%32];"
        : "=r"(r[0]),  "=r"(r[1]),  "=r"(r[2]),  "=r"(r[3]),
          "=r"(r[4]),  "=r"(r[5]),  "=r"(r[6]),  "=r"(r[7]),
          "=r"(r[8]),  "=r"(r[9]),  "=r"(r[10]), "=r"(r[11]),
          "=r"(r[12]), "=r"(r[13]), "=r"(r[14]), "=r"(r[15]),
          "=r"(r[16]), "=r"(r[17]), "=r"(r[18]), "=r"(r[19]),
          "=r"(r[20]), "=r"(r[21]), "=r"(r[22]), "=r"(r[23]),
          "=r"(r[24]), "=r"(r[25]), "=r"(r[26]), "=r"(r[27]),
          "=r"(r[28]), "=r"(r[29]), "=r"(r[30]), "=r"(r[31])
        : "r"(ta));
#else
    for (int i = 0; i < 32; i++) r[i] = 0u;
    (void)ta;
#endif
}
static __device__ __forceinline__ uint64_t mk_desc(uint32_t addr) {
    // K-major SW128: LBO=1 (16B), SBO=64 (1024B / 8-row atom)
    const uint64_t BASE = (2ull << 61) | (1ull << 46) | (64ull << 32) | (1ull << 16);
    return BASE | ((uint64_t)(addr >> 4) & 0x3FFF);
}
static __device__ __forceinline__ void cp16(uint32_t dst, const void* src) {
    asm volatile("cp.async.cg.shared.global [%0], [%1], 16;"
                 :: "r"(dst), "l"(src) : "memory");
}
static __device__ __forceinline__ void cp_commit() {
    asm volatile("cp.async.commit_group;" ::: "memory");
}
static __device__ __forceinline__ void cp_wait1() {
    asm volatile("cp.async.wait_group 1;" ::: "memory");
}
static __device__ __forceinline__ void cp_wait0() {
    asm volatile("cp.async.wait_group 0;" ::: "memory");
}

// ---------------------------------------------------------------------------
// fp32 -> (bf16 hi, bf16 lo)
// ---------------------------------------------------------------------------
__global__ __launch_bounds__(256) void split_kernel(
    const float* __restrict__ in, __nv_bfloat16* __restrict__ hi,
    __nv_bfloat16* __restrict__ lo, int n)
{
    int stride = gridDim.x * blockDim.x * 4;
    for (int i = (blockIdx.x * blockDim.x + threadIdx.x) * 4; i < n; i += stride) {
        float4 x = *(const float4*)(in + i);
        __nv_bfloat16 h0 = __float2bfloat16(x.x);
        __nv_bfloat16 h1 = __float2bfloat16(x.y);
        __nv_bfloat16 h2 = __float2bfloat16(x.z);
        __nv_bfloat16 h3 = __float2bfloat16(x.w);
        __nv_bfloat16 l0 = __float2bfloat16(x.x - __bfloat162float(h0));
        __nv_bfloat16 l1 = __float2bfloat16(x.y - __bfloat162float(h1));
        __nv_bfloat16 l2 = __float2bfloat16(x.z - __bfloat162float(h2));
        __nv_bfloat16 l3 = __float2bfloat16(x.w - __bfloat162float(h3));
        __nv_bfloat162* hp = (__nv_bfloat162*)(hi + i);
        __nv_bfloat162* lp = (__nv_bfloat162*)(lo + i);
        hp[0] = __nv_bfloat162(h0, h1); hp[1] = __nv_bfloat162(h2, h3);
        lp[0] = __nv_bfloat162(l0, l1); lp[1] = __nv_bfloat162(l2, l3);
    }
}

// ---------------------------------------------------------------------------
// tcgen05 bf16x3 GEMM, cp.async 3-stage pipeline.
// C = Ah@Bh^T + Ah@Bl^T + Al@Bh^T, fp32 TMEM accum, 128x128 tile per CTA.
// Last chunk uses wait_group 0 (only one group in flight there).
// ---------------------------------------------------------------------------
#define GCHUNK   64
#define GTILE_B  16384
#define GSTAGE_B (4 * GTILE_B)          // 65536
#define GCTRL    (3 * GSTAGE_B)         // 196608
#define GSMEM    (GCTRL + 64)

__global__ __launch_bounds__(256) void gemm_tc_kernel(
    const __nv_bfloat16* __restrict__ Ah, const __nv_bfloat16* __restrict__ Al,
    const __nv_bfloat16* __restrict__ Bh, const __nv_bfloat16* __restrict__ Bl,
    float* __restrict__ C, int N, int K)
{
    extern __shared__ char sm_raw[];
    const uint32_t sb  = s2u(sm_raw);
    const int tid = threadIdx.x;
    const int wid = tid >> 5;
    const int m0  = blockIdx.y * 128;
    const int n0  = blockIdx.x * 128;

    if (wid == 0) { tc_alloc(sb + GCTRL + 32, 128); tc_relinq(); }
    if (tid == 0) {
        mbar_init(sb + GCTRL + 0, 1);
        mbar_init(sb + GCTRL + 8, 1);
        mbar_init(sb + GCTRL + 16, 1);
    }
    __syncthreads();
    uint32_t tmem;
    asm volatile("ld.shared.b32 %0, [%1];" : "=r"(tmem) : "r"(sb + GCTRL + 32));

    const uint32_t idesc = (1u << 4) | (1u << 7) | (1u << 10) |
                           ((128u / 8) << 17) | ((128u / 16) << 24);

    const int KW = K >> 3;
    const int g  = tid & 7;
    const int rb = tid >> 3;            // 0..31
    const int sc = g ^ (rb & 7);
    const size_t a4 = (((size_t)(m0 + rb) * K) >> 3) + g;
    const size_t b4 = (((size_t)(n0 + rb) * K) >> 3) + g;
    const uint4* srcs[4] = { (const uint4*)Ah, (const uint4*)Al,
                             (const uint4*)Bh, (const uint4*)Bl };
    const uint32_t dbase = sb + (rb * 8 + sc) * 16;

    const int NCH = K / GCHUNK;

    auto load_chunk = [&](int c, int s) {
        const size_t ko4 = (size_t)c * 8;
#pragma unroll
        for (int t = 0; t < 4; t++) {
            const size_t base = ((t < 2) ? a4 : b4) + ko4;
            const uint4* sp = srcs[t];
            const uint32_t d0 = dbase + s * GSTAGE_B + t * GTILE_B;
#pragma unroll
            for (int r = 0; r < 4; r++)
                cp16(d0 + r * 32 * 128, sp + base + (size_t)(32 * r) * KW);
        }
        cp_commit();
    };

    load_chunk(0, 0);
    load_chunk(1, 1);

    int par[3] = {0, 0, 0};
    for (int c = 0; c < NCH; c++) {
        const int s = c % 3;
        if (c == NCH - 1) cp_wait0(); else cp_wait1();
        __syncthreads();
        if (wid == 0 && elect1()) {
            fence_async();
            tc_fence_after();
            const uint32_t sa = sb + s * GSTAGE_B;
            const uint64_t dAh = mk_desc(sa);
            const uint64_t dAl = mk_desc(sa + GTILE_B);
            const uint64_t dBh = mk_desc(sa + 2 * GTILE_B);
            const uint64_t dBl = mk_desc(sa + 3 * GTILE_B);
#pragma unroll
            for (int ks = 0; ks < 4; ks++)
                tc_mma_f16_ss(tmem, dAh + ks * 2, dBh + ks * 2, idesc,
                              (c == 0 && ks == 0) ? 0u : 1u);
#pragma unroll
            for (int ks = 0; ks < 4; ks++)
                tc_mma_f16_ss(tmem, dAh + ks * 2, dBl + ks * 2, idesc, 1u);
#pragma unroll
            for (int ks = 0; ks < 4; ks++)
                tc_mma_f16_ss(tmem, dAl + ks * 2, dBh + ks * 2, idesc, 1u);
            tc_commit(sb + GCTRL + s * 8);
        }
        if (c + 2 < NCH) {
            if (c >= 1) {
                int ws = (c - 1) % 3;
                mbar_wait(sb + GCTRL + ws * 8, par[ws]);
                par[ws] ^= 1;
            }
            load_chunk(c + 2, (c + 2) % 3);
        }
    }

    {   // wait for the final chunk's MMAs
        int sl = (NCH - 1) % 3;
        int q  = (NCH - 1 - sl) / 3 + 1;
        mbar_wait(sb + GCTRL + sl * 8, (q - 1) & 1);
    }
    tc_fence_after();

    if (tid < 128) {
#pragma unroll
        for (int cb = 0; cb < 4; cb++) {
            uint32_t dr[32];
            tc_ld32(dr, tmem + cb * 32);
            tc_waitld();
            float* cp = C + (size_t)(m0 + tid) * N + n0 + cb * 32;
#pragma unroll
            for (int j = 0; j < 32; j += 4)
                *(float4*)(cp + j) = make_float4(
                    __uint_as_float(dr[j]), __uint_as_float(dr[j + 1]),
                    __uint_as_float(dr[j + 2]), __uint_as_float(dr[j + 3]));
        }
        tc_fence_before();
    }
    __syncthreads();
    if (wid == 0) tc_dealloc(tmem, 128);
}

// ---------------------------------------------------------------------------
// RoPE (NeoX rotate-half) applied in place to q (32 heads) and k (8 heads).
// (round-3 verified version)
// ---------------------------------------------------------------------------
__global__ __launch_bounds__(256) void rope_kernel(float* __restrict__ q,
                                                   float* __restrict__ k)
{
    __shared__ float sInv[64];
    const int t = blockIdx.x;
    if (threadIdx.x < 64)
        sInv[threadIdx.x] =
            (float)exp2(-(double)threadIdx.x * 0.20762050593045952); // log2(1e4)/64
    __syncthreads();

    for (int p = threadIdx.x; p < (NH + HKV) * 64; p += 256) {
        float* base;
        int d;
        if (p < NH * 64) {
            base = q + (size_t)t * INNER + (p >> 6) * HD;
            d = p & 63;
        } else {
            int pp = p - NH * 64;
            base = k + (size_t)t * KVI + (pp >> 6) * HD;
            d = pp & 63;
        }
        float ang = (float)t * sInv[d];
        float s, c;
        sincosf(ang, &s, &c);
        float x1 = base[d], x2 = base[d + 64];
        base[d]      = x1 * c - x2 * s;
        base[d + 64] = x2 * c + x1 * s;
    }
}

// ---------------------------------------------------------------------------
// Causal flash attention, fp32 (round-3 verified version, unchanged).
// ---------------------------------------------------------------------------
__global__ __launch_bounds__(256) void attn_kernel(
    const float* __restrict__ Q, const float* __restrict__ Kg,
    const float* __restrict__ Vg, float* __restrict__ O)
{
    extern __shared__ float sm[];
    float* sQ   = sm;            // 64*128
    float* sKV  = sm + 8192;     // 64*128, swizzled (K then reused for V)
    float* sP   = sm + 16384;    // 64*64
    float* sRed = sm + 20480;    // 64*17

    const int h   = blockIdx.y;
    const int qb  = blockIdx.x;
    const int hk  = h >> 2;
    const int q0  = qb * 64;
    const int tid = threadIdx.x;
    const int tr  = tid >> 4;
    const int tc  = tid & 15;

#pragma unroll
    for (int it = 0; it < 8; it++) {
        int idx = tid + it * 256;
        int row = idx >> 5, dg = idx & 31;
        *(float4*)(sQ + row * 128 + dg * 4) =
            *(const float4*)(Q + (size_t)(q0 + row) * INNER + h * HD + dg * 4);
    }

    float m_i[4], l_i[4], acc[4][8];
#pragma unroll
    for (int i = 0; i < 4; i++) {
        m_i[i] = -INFINITY;
        l_i[i] = 0.f;
#pragma unroll
        for (int j = 0; j < 8; j++) acc[i][j] = 0.f;
    }
    const float scale = 0.08838834764831845f;

    for (int kt = 0; kt <= qb; kt++) {
        const int k0 = kt * 64;
        __syncthreads();

#pragma unroll
        for (int it = 0; it < 8; it++) {
            int idx = tid + it * 256;
            int row = idx >> 5, dg = idx & 31;
            int slot = dg ^ ((row >> 2) & 7);
            *(float4*)(sKV + row * 128 + slot * 4) =
                *(const float4*)(Kg + (size_t)(k0 + row) * KVI + hk * HD + dg * 4);
        }
        __syncthreads();

        float s[4][4];
#pragma unroll
        for (int i = 0; i < 4; i++)
#pragma unroll
            for (int j = 0; j < 4; j++) s[i][j] = 0.f;

#pragma unroll 4
        for (int dg = 0; dg < 32; dg++) {
            float4 q4[4], k4[4];
            int slot = (dg ^ (tc & 7)) * 4;
#pragma unroll
            for (int i = 0; i < 4; i++)
                q4[i] = *(const float4*)(sQ + (4 * tr + i) * 128 + dg * 4);
#pragma unroll
            for (int j = 0; j < 4; j++)
                k4[j] = *(const float4*)(sKV + (4 * tc + j) * 128 + slot);
#pragma unroll
            for (int i = 0; i < 4; i++)
#pragma unroll
                for (int j = 0; j < 4; j++)
                    s[i][j] += q4[i].x * k4[j].x + q4[i].y * k4[j].y +
                               q4[i].z * k4[j].z + q4[i].w * k4[j].w;
        }

        if (kt == qb) {
#pragma unroll
            for (int i = 0; i < 4; i++)
#pragma unroll
                for (int j = 0; j < 4; j++)
                    s[i][j] = (k0 + 4 * tc + j > q0 + 4 * tr + i)
                                  ? -1e30f : s[i][j] * scale;
        } else {
#pragma unroll
            for (int i = 0; i < 4; i++)
#pragma unroll
                for (int j = 0; j < 4; j++) s[i][j] *= scale;
        }

#pragma unroll
        for (int i = 0; i < 4; i++) {
            float mx = fmaxf(fmaxf(s[i][0], s[i][1]), fmaxf(s[i][2], s[i][3]));
            sRed[(4 * tr + i) * 17 + tc] = mx;
        }
        __syncthreads();

#pragma unroll
        for (int it = 0; it < 8; it++) {
            int idx = tid + it * 256;
            int row = idx >> 5, dg = idx & 31;
            int slot = dg ^ ((row >> 2) & 7);
            *(float4*)(sKV + row * 128 + slot * 4) =
                *(const float4*)(Vg + (size_t)(k0 + row) * KVI + hk * HD + dg * 4);
        }

        float newm[4];
#pragma unroll
        for (int i = 0; i < 4; i++) {
            float mx = m_i[i];
            const float* rr = sRed + (4 * tr + i) * 17;
#pragma unroll
            for (int t2 = 0; t2 < 16; t2++) mx = fmaxf(mx, rr[t2]);
            newm[i] = mx;
        }
        __syncthreads();

#pragma unroll
        for (int i = 0; i < 4; i++) {
            float su = 0.f;
#pragma unroll
            for (int j = 0; j < 4; j++) {
                float p = __expf(s[i][j] - newm[i]);
                sP[(4 * tr + i) * 64 + 4 * tc + j] = p;
                su += p;
            }
            sRed[(4 * tr + i) * 17 + tc] = su;
        }
        __syncthreads();

#pragma unroll
        for (int i = 0; i < 4; i++) {
            float su = 0.f;
            const float* rr = sRed + (4 * tr + i) * 17;
#pragma unroll
            for (int t2 = 0; t2 < 16; t2++) su += rr[t2];
            float corr = __expf(m_i[i] - newm[i]);
            l_i[i] = l_i[i] * corr + su;
            m_i[i] = newm[i];
#pragma unroll
            for (int j = 0; j < 8; j++) acc[i][j] *= corr;
        }

#pragma unroll 2
        for (int kk = 0; kk < 64; kk++) {
            int sl = (kk >> 2) & 7;
            int sa = tc ^ sl;
            float4 va = *(const float4*)(sKV + kk * 128 + sa * 4);
            float4 vb = *(const float4*)(sKV + kk * 128 + (sa + 16) * 4);
#pragma unroll
            for (int i = 0; i < 4; i++) {
                float p = sP[(4 * tr + i) * 64 + kk];
                acc[i][0] += p * va.x; acc[i][1] += p * va.y;
                acc[i][2] += p * va.z; acc[i][3] += p * va.w;
                acc[i][4] += p * vb.x; acc[i][5] += p * vb.y;
                acc[i][6] += p * vb.z; acc[i][7] += p * vb.w;
            }
        }
    }

#pragma unroll
    for (int i = 0; i < 4; i++) {
        float inv = 1.f / l_i[i];
        float4 c0 = make_float4(acc[i][0] * inv, acc[i][1] * inv,
                                acc[i][2] * inv, acc[i][3] * inv);
        float4 c1 = make_float4(acc[i][4] * inv, acc[i][5] * inv,
                                acc[i][6] * inv, acc[i][7] * inv);
        size_t base = (size_t)(q0 + 4 * tr + i) * INNER + h * HD;
        *(float4*)(O + base + tc * 4) = c0;
        *(float4*)(O + base + 64 + tc * 4) = c1;
    }
}

// ---------------------------------------------------------------------------
extern "C" void kernel_launch(void* const* d_in, const int* in_sizes, int n_in,
                              void* d_out, int out_size)
{
    (void)in_sizes; (void)n_in; (void)out_size;
    const float* stm = (const float*)d_in[0];
    const float* w_q = (const float*)d_in[1];
    const float* w_k = (const float*)d_in[2];
    const float* w_v = (const float*)d_in[3];
    const float* w_o = (const float*)d_in[4];
    float* out = (float*)d_out;

    float *pq, *pk, *pv, *pa;
    cudaGetSymbolAddress((void**)&pq, g_q);
    cudaGetSymbolAddress((void**)&pk, g_k);
    cudaGetSymbolAddress((void**)&pv, g_v);
    cudaGetSymbolAddress((void**)&pa, g_ao);

    __nv_bfloat16 *xh, *xl, *wqh, *wql, *wkh, *wkl, *wvh, *wvl, *woh, *wol, *aoh, *aol;
    cudaGetSymbolAddress((void**)&xh,  g_xh);  cudaGetSymbolAddress((void**)&xl,  g_xl);
    cudaGetSymbolAddress((void**)&wqh, g_wqh); cudaGetSymbolAddress((void**)&wql, g_wql);
    cudaGetSymbolAddress((void**)&wkh, g_wkh); cudaGetSymbolAddress((void**)&wkl, g_wkl);
    cudaGetSymbolAddress((void**)&wvh, g_wvh); cudaGetSymbolAddress((void**)&wvl, g_wvl);
    cudaGetSymbolAddress((void**)&woh, g_woh); cudaGetSymbolAddress((void**)&wol, g_wol);
    cudaGetSymbolAddress((void**)&aoh, g_aoh); cudaGetSymbolAddress((void**)&aol, g_aol);

    const int attn_smem = (8192 + 8192 + 4096 + 64 * 17) * 4; // 86272 B
    cudaFuncSetAttribute(attn_kernel,
                         cudaFuncAttributeMaxDynamicSharedMemorySize, attn_smem);
    cudaFuncSetAttribute(gemm_tc_kernel,
                         cudaFuncAttributeMaxDynamicSharedMemorySize, GSMEM);

    // Splits
    split_kernel<<<4096, 256>>>(stm, xh,  xl,  T_LEN * INNER);
    split_kernel<<<4096, 256>>>(w_q, wqh, wql, INNER * INNER);
    split_kernel<<<4096, 256>>>(w_k, wkh, wkl, KVI * INNER);
    split_kernel<<<4096, 256>>>(w_v, wvh, wvl, KVI * INNER);
    split_kernel<<<4096, 256>>>(w_o, woh, wol, INNER * INNER);

    // Projections (tcgen05 bf16x3, cp.async pipeline)
    gemm_tc_kernel<<<dim3(INNER / 128, T_LEN / 128), 256, GSMEM>>>(
        xh, xl, wqh, wql, pq, INNER, INNER);
    gemm_tc_kernel<<<dim3(KVI / 128, T_LEN / 128), 256, GSMEM>>>(
        xh, xl, wkh, wkl, pk, KVI, INNER);
    gemm_tc_kernel<<<dim3(KVI / 128, T_LEN / 128), 256, GSMEM>>>(
        xh, xl, wvh, wvl, pv, KVI, INNER);

    rope_kernel<<<T_LEN, 256>>>(pq, pk);

    attn_kernel<<<dim3(T_LEN / 64, NH), 256, attn_smem>>>(pq, pk, pv, pa);

    split_kernel<<<4096, 256>>>(pa, aoh, aol, T_LEN * INNER);
    gemm_tc_kernel<<<dim3(INNER / 128, T_LEN / 128), 256, GSMEM>>>(
        aoh, aol, woh, wol, out, INNER, INNER);
}

// round 7
// speedup vs baseline: 7.9841x; 2.3931x over previous
#include <cuda_runtime.h>
#include <cuda_bf16.h>
#include <math.h>
#include <cstdint>
#include <cstddef>

// Problem constants
#define T_LEN 2048
#define NH    32
#define HKV   8
#define HD    128
#define INNER 4096      // NH*HD
#define KVI   1024      // HKV*HD

// tcgen05 only exists in the compute_103a pass; the plain compute_103 JIT
// fallback pass compiles these as stubs (never executed on GB300).
#if defined(__CUDA_ARCH_FEAT_SM103_ALL) || defined(__CUDA_ARCH_FEAT_SM100_ALL)
#define TC_OK 1
#else
#define TC_OK 0
#endif

// ---------------------------------------------------------------------------
// Scratch (device globals: no allocation allowed)
// ---------------------------------------------------------------------------
__device__ float g_q [T_LEN * INNER];
__device__ float g_k [T_LEN * KVI];

__device__ __nv_bfloat16 g_xh [T_LEN * INNER], g_xl [T_LEN * INNER];
__device__ __nv_bfloat16 g_wqh[INNER * INNER], g_wql[INNER * INNER];
__device__ __nv_bfloat16 g_wkh[KVI  * INNER], g_wkl[KVI  * INNER];
__device__ __nv_bfloat16 g_wvh[KVI  * INNER], g_wvl[KVI  * INNER];
__device__ __nv_bfloat16 g_woh[INNER * INNER], g_wol[INNER * INNER];

__device__ __nv_bfloat16 g_qh [T_LEN * INNER], g_ql [T_LEN * INNER];
__device__ __nv_bfloat16 g_kh [T_LEN * KVI],  g_kl [T_LEN * KVI];
__device__ __nv_bfloat16 g_vth[KVI * T_LEN],  g_vtl[KVI * T_LEN];   // V^T [dim][t]
__device__ __nv_bfloat16 g_aoh[T_LEN * INNER], g_aol[T_LEN * INNER];

// ---------------------------------------------------------------------------
// PTX helpers (sm_103a)
// ---------------------------------------------------------------------------
static __device__ __forceinline__ uint32_t s2u(const void* p) {
    uint32_t a;
    asm("{ .reg .u64 t; cvta.to.shared.u64 t, %1; cvt.u32.u64 %0, t; }"
        : "=r"(a) : "l"(p));
    return a;
}
static __device__ __forceinline__ uint32_t elect1() {
    uint32_t p;
    asm volatile("{ .reg .pred p; elect.sync _|p, 0xFFFFFFFF; selp.b32 %0,1,0,p; }"
                 : "=r"(p));
    return p;
}
static __device__ __forceinline__ void mbar_init(uint32_t a, uint32_t n) {
    asm volatile("mbarrier.init.shared.b64 [%0], %1;" :: "r"(a), "r"(n) : "memory");
}
static __device__ __forceinline__ void mbar_wait(uint32_t a, uint32_t par) {
    asm volatile(
        "{\n\t.reg .pred P;\n\t"
        "LAB%=:\n\t"
        "mbarrier.try_wait.parity.acquire.cta.shared::cta.b64 P, [%0], %1, 0x989680;\n\t"
        "@P bra DONE%=;\n\t"
        "bra LAB%=;\n\t"
        "DONE%=:\n\t}"
        :: "r"(a), "r"(par) : "memory");
}
static __device__ __forceinline__ void tc_alloc(uint32_t smem_addr, uint32_t ncols) {
#if TC_OK
    asm volatile("tcgen05.alloc.cta_group::1.sync.aligned.shared::cta.b32 [%0], %1;"
                 :: "r"(smem_addr), "r"(ncols) : "memory");
#endif
}
static __device__ __forceinline__ void tc_relinq() {
#if TC_OK
    asm volatile("tcgen05.relinquish_alloc_permit.cta_group::1.sync.aligned;");
#endif
}
static __device__ __forceinline__ void tc_dealloc(uint32_t tmem, uint32_t ncols) {
#if TC_OK
    asm volatile("tcgen05.dealloc.cta_group::1.sync.aligned.b32 %0, %1;"
                 :: "r"(tmem), "r"(ncols));
#endif
}
static __device__ __forceinline__ void tc_commit(uint32_t mbar) {
#if TC_OK
    asm volatile("tcgen05.commit.cta_group::1.mbarrier::arrive::one.shared::cluster.b64 [%0];"
                 :: "r"(mbar) : "memory");
#endif
}
static __device__ __forceinline__ void tc_mma_f16_ss(uint32_t d, uint64_t ad, uint64_t bd,
                                                     uint32_t idesc, uint32_t en) {
#if TC_OK
    asm volatile(
        "{\n\t.reg .pred p;\n\t"
        "setp.ne.u32 p, %4, 0;\n\t"
        "tcgen05.mma.cta_group::1.kind::f16 [%0], %1, %2, %3, {%5,%5,%5,%5}, p;\n\t}"
        :: "r"(d), "l"(ad), "l"(bd), "r"(idesc), "r"(en), "r"(0u) : "memory");
#endif
}
static __device__ __forceinline__ void tc_mma_f16_ts(uint32_t d, uint32_t a, uint64_t bd,
                                                     uint32_t idesc, uint32_t en) {
#if TC_OK
    asm volatile(
        "{\n\t.reg .pred p;\n\t"
        "setp.ne.u32 p, %4, 0;\n\t"
        "tcgen05.mma.cta_group::1.kind::f16 [%0], [%1], %2, %3, {%5,%5,%5,%5}, p;\n\t}"
        :: "r"(d), "r"(a), "l"(bd), "r"(idesc), "r"(en), "r"(0u) : "memory");
#endif
}
static __device__ __forceinline__ void tc_waitld() {
#if TC_OK
    asm volatile("tcgen05.wait::ld.sync.aligned;" ::: "memory");
#endif
}
static __device__ __forceinline__ void tc_waitst() {
#if TC_OK
    asm volatile("tcgen05.wait::st.sync.aligned;" ::: "memory");
#endif
}
static __device__ __forceinline__ void tc_fence_after() {
#if TC_OK
    asm volatile("tcgen05.fence::after_thread_sync;" ::: "memory");
#endif
}
static __device__ __forceinline__ void tc_fence_before() {
#if TC_OK
    asm volatile("tcgen05.fence::before_thread_sync;" ::: "memory");
#endif
}
static __device__ __forceinline__ void fence_async() {
    asm volatile("fence.proxy.async.shared::cta;" ::: "memory");
}
static __device__ __forceinline__ void tc_ld32(uint32_t* r, uint32_t ta) {
#if TC_OK
    asm volatile(
        "tcgen05.ld.sync.aligned.32x32b.x32.b32 "
        "{%0, %1, %2, %3, %4, %5, %6, %7, "
        " %8, %9, %10, %11, %12, %13, %14, %15, "
        " %16, %17, %18, %19, %20, %21, %22, %23, "
        " %24, %25, %26, %27, %28, %29, %30, %31}, [%32];"
        : "=r"(r[0]),  "=r"(r[1]),  "=r"(r[2]),  "=r"(r[3]),
          "=r"(r[4]),  "=r"(r[5]),  "=r"(r[6]),  "=r"(r[7]),
          "=r"(r[8]),  "=r"(r[9]),  "=r"(r[10]), "=r"(r[11]),
          "=r"(r[12]), "=r"(r[13]), "=r"(r[14]), "=r"(r[15]),
          "=r"(r[16]), "=r"(r[17]), "=r"(r[18]), "=r"(r[19]),
          "=r"(r[20]), "=r"(r[21]), "=r"(r[22]), "=r"(r[23]),
          "=r"(r[24]), "=r"(r[25]), "=r"(r[26]), "=r"(r[27]),
          "=r"(r[28]), "=r"(r[29]), "=r"(r[30]), "=r"(r[31])
        : "r"(ta));
#else
    for (int i = 0; i < 32; i++) r[i] = 0u;
    (void)ta;
#endif
}
static __device__ __forceinline__ void tc_st16(uint32_t ta, const uint32_t* r) {
#if TC_OK
    asm volatile(
        "tcgen05.st.sync.aligned.32x32b.x16.b32 [%0], "
        "{%1, %2, %3, %4, %5, %6, %7, %8, "
        " %9, %10, %11, %12, %13, %14, %15, %16};"
        :: "r"(ta),
           "r"(r[0]),  "r"(r[1]),  "r"(r[2]),  "r"(r[3]),
           "r"(r[4]),  "r"(r[5]),  "r"(r[6]),  "r"(r[7]),
           "r"(r[8]),  "r"(r[9]),  "r"(r[10]), "r"(r[11]),
           "r"(r[12]), "r"(r[13]), "r"(r[14]), "r"(r[15])
        : "memory");
#else
    (void)ta; (void)r;
#endif
}
static __device__ __forceinline__ uint64_t mk_desc(uint32_t addr) {
    // K-major SW128: LBO=1 (16B), SBO=64 (1024B / 8-row atom)
    const uint64_t BASE = (2ull << 61) | (1ull << 46) | (64ull << 32) | (1ull << 16);
    return BASE | ((uint64_t)(addr >> 4) & 0x3FFF);
}
static __device__ __forceinline__ void cp16(uint32_t dst, const void* src) {
    asm volatile("cp.async.cg.shared.global [%0], [%1], 16;"
                 :: "r"(dst), "l"(src) : "memory");
}
static __device__ __forceinline__ void cp_commit() {
    asm volatile("cp.async.commit_group;" ::: "memory");
}
static __device__ __forceinline__ void cp_wait1() {
    asm volatile("cp.async.wait_group 1;" ::: "memory");
}
static __device__ __forceinline__ void cp_wait0() {
    asm volatile("cp.async.wait_group 0;" ::: "memory");
}
static __device__ __forceinline__ uint32_t pk2(__nv_bfloat16 a, __nv_bfloat16 b) {
    __nv_bfloat162 t(a, b);
    return *(uint32_t*)&t;
}

// ---------------------------------------------------------------------------
// fp32 -> (bf16 hi, bf16 lo)
// ---------------------------------------------------------------------------
__global__ __launch_bounds__(256) void split_kernel(
    const float* __restrict__ in, __nv_bfloat16* __restrict__ hi,
    __nv_bfloat16* __restrict__ lo, int n)
{
    int stride = gridDim.x * blockDim.x * 4;
    for (int i = (blockIdx.x * blockDim.x + threadIdx.x) * 4; i < n; i += stride) {
        float4 x = *(const float4*)(in + i);
        __nv_bfloat16 h0 = __float2bfloat16(x.x);
        __nv_bfloat16 h1 = __float2bfloat16(x.y);
        __nv_bfloat16 h2 = __float2bfloat16(x.z);
        __nv_bfloat16 h3 = __float2bfloat16(x.w);
        __nv_bfloat16 l0 = __float2bfloat16(x.x - __bfloat162float(h0));
        __nv_bfloat16 l1 = __float2bfloat16(x.y - __bfloat162float(h1));
        __nv_bfloat16 l2 = __float2bfloat16(x.z - __bfloat162float(h2));
        __nv_bfloat16 l3 = __float2bfloat16(x.w - __bfloat162float(h3));
        __nv_bfloat162* hp = (__nv_bfloat162*)(hi + i);
        __nv_bfloat162* lp = (__nv_bfloat162*)(lo + i);
        hp[0] = __nv_bfloat162(h0, h1); hp[1] = __nv_bfloat162(h2, h3);
        lp[0] = __nv_bfloat162(l0, l1); lp[1] = __nv_bfloat162(l2, l3);
    }
}

// ---------------------------------------------------------------------------
// tcgen05 bf16x3 GEMM, cp.async 3-stage pipeline (round-6 verified).
// OUTB=0: fp32 C[m][n].  OUTB=2: transposed bf16 hi/lo Ct[n][m] (for V^T).
// ---------------------------------------------------------------------------
#define GCHUNK   64
#define GTILE_B  16384
#define GSTAGE_B (4 * GTILE_B)          // 65536
#define GCTRL    (3 * GSTAGE_B)         // 196608
#define GSMEM    (GCTRL + 64)

template<int OUTB>
__global__ __launch_bounds__(256) void gemm_tc_kernel(
    const __nv_bfloat16* __restrict__ Ah, const __nv_bfloat16* __restrict__ Al,
    const __nv_bfloat16* __restrict__ Bh, const __nv_bfloat16* __restrict__ Bl,
    float* __restrict__ C, __nv_bfloat16* __restrict__ Cht,
    __nv_bfloat16* __restrict__ Clt, int N, int K)
{
    extern __shared__ char sm_raw[];
    const uint32_t sb  = s2u(sm_raw);
    const int tid = threadIdx.x;
    const int wid = tid >> 5;
    const int m0  = blockIdx.y * 128;
    const int n0  = blockIdx.x * 128;

    if (wid == 0) { tc_alloc(sb + GCTRL + 32, 128); tc_relinq(); }
    if (tid == 0) {
        mbar_init(sb + GCTRL + 0, 1);
        mbar_init(sb + GCTRL + 8, 1);
        mbar_init(sb + GCTRL + 16, 1);
    }
    __syncthreads();
    uint32_t tmem;
    asm volatile("ld.shared.b32 %0, [%1];" : "=r"(tmem) : "r"(sb + GCTRL + 32));

    const uint32_t idesc = (1u << 4) | (1u << 7) | (1u << 10) |
                           ((128u / 8) << 17) | ((128u / 16) << 24);

    const int KW = K >> 3;
    const int g  = tid & 7;
    const int rb = tid >> 3;            // 0..31
    const int sc = g ^ (rb & 7);
    const size_t a4 = (((size_t)(m0 + rb) * K) >> 3) + g;
    const size_t b4 = (((size_t)(n0 + rb) * K) >> 3) + g;
    const uint4* srcs[4] = { (const uint4*)Ah, (const uint4*)Al,
                             (const uint4*)Bh, (const uint4*)Bl };
    const uint32_t dbase = sb + (rb * 8 + sc) * 16;

    const int NCH = K / GCHUNK;

    auto load_chunk = [&](int c, int s) {
        const size_t ko4 = (size_t)c * 8;
#pragma unroll
        for (int t = 0; t < 4; t++) {
            const size_t base = ((t < 2) ? a4 : b4) + ko4;
            const uint4* sp = srcs[t];
            const uint32_t d0 = dbase + s * GSTAGE_B + t * GTILE_B;
#pragma unroll
            for (int r = 0; r < 4; r++)
                cp16(d0 + r * 32 * 128, sp + base + (size_t)(32 * r) * KW);
        }
        cp_commit();
    };

    load_chunk(0, 0);
    load_chunk(1, 1);

    int par[3] = {0, 0, 0};
    for (int c = 0; c < NCH; c++) {
        const int s = c % 3;
        if (c == NCH - 1) cp_wait0(); else cp_wait1();
        __syncthreads();
        if (wid == 0 && elect1()) {
            fence_async();
            tc_fence_after();
            const uint32_t sa = sb + s * GSTAGE_B;
            const uint64_t dAh = mk_desc(sa);
            const uint64_t dAl = mk_desc(sa + GTILE_B);
            const uint64_t dBh = mk_desc(sa + 2 * GTILE_B);
            const uint64_t dBl = mk_desc(sa + 3 * GTILE_B);
#pragma unroll
            for (int ks = 0; ks < 4; ks++)
                tc_mma_f16_ss(tmem, dAh + ks * 2, dBh + ks * 2, idesc,
                              (c == 0 && ks == 0) ? 0u : 1u);
#pragma unroll
            for (int ks = 0; ks < 4; ks++)
                tc_mma_f16_ss(tmem, dAh + ks * 2, dBl + ks * 2, idesc, 1u);
#pragma unroll
            for (int ks = 0; ks < 4; ks++)
                tc_mma_f16_ss(tmem, dAl + ks * 2, dBh + ks * 2, idesc, 1u);
            tc_commit(sb + GCTRL + s * 8);
        }
        if (c + 2 < NCH) {
            if (c >= 1) {
                int ws = (c - 1) % 3;
                mbar_wait(sb + GCTRL + ws * 8, par[ws]);
                par[ws] ^= 1;
            }
            load_chunk(c + 2, (c + 2) % 3);
        }
    }

    {   // wait for the final chunk's MMAs
        int sl = (NCH - 1) % 3;
        int q  = (NCH - 1 - sl) / 3 + 1;
        mbar_wait(sb + GCTRL + sl * 8, (q - 1) & 1);
    }
    tc_fence_after();

    if (tid < 128) {
#pragma unroll
        for (int cb = 0; cb < 4; cb++) {
            uint32_t dr[32];
            tc_ld32(dr, tmem + cb * 32);
            tc_waitld();
            if (OUTB == 0) {
                float* cp = C + (size_t)(m0 + tid) * N + n0 + cb * 32;
#pragma unroll
                for (int j = 0; j < 32; j += 4)
                    *(float4*)(cp + j) = make_float4(
                        __uint_as_float(dr[j]), __uint_as_float(dr[j + 1]),
                        __uint_as_float(dr[j + 2]), __uint_as_float(dr[j + 3]));
            } else {
                // transposed bf16 hi/lo: Ct[n][m], coalesced along m (=tid)
#pragma unroll
                for (int j = 0; j < 32; j++) {
                    float f = __uint_as_float(dr[j]);
                    __nv_bfloat16 hv = __float2bfloat16(f);
                    __nv_bfloat16 lv = __float2bfloat16(f - __bfloat162float(hv));
                    size_t idx = (size_t)(n0 + cb * 32 + j) * T_LEN + m0 + tid;
                    Cht[idx] = hv;
                    Clt[idx] = lv;
                }
            }
        }
        tc_fence_before();
    }
    __syncthreads();
    if (wid == 0) tc_dealloc(tmem, 128);
}

// ---------------------------------------------------------------------------
// RoPE -> pre-scaled bf16 hi/lo Q (x 1/sqrt(128)) and bf16 hi/lo K.
// ---------------------------------------------------------------------------
__global__ __launch_bounds__(256) void rope_kernel(
    const float* __restrict__ q, const float* __restrict__ k,
    __nv_bfloat16* __restrict__ qh, __nv_bfloat16* __restrict__ ql,
    __nv_bfloat16* __restrict__ kh, __nv_bfloat16* __restrict__ kl)
{
    __shared__ float sInv[64];
    const int t = blockIdx.x;
    if (threadIdx.x < 64)
        sInv[threadIdx.x] =
            (float)exp2(-(double)threadIdx.x * 0.20762050593045952);
    __syncthreads();
    const float SC = 0.08838834764831845f;

    for (int p = threadIdx.x; p < (NH + HKV) * 64; p += 256) {
        int d = p & 63;
        float ang = (float)t * sInv[d];
        float s, c;
        sincosf(ang, &s, &c);
        size_t off; const float* base; __nv_bfloat16 *oh, *ol; float sc2;
        if (p < NH * 64) {
            off = (size_t)t * INNER + (p >> 6) * HD;
            base = q + off; oh = qh + off; ol = ql + off; sc2 = SC;
        } else {
            int pp = p - NH * 64;
            off = (size_t)t * KVI + (pp >> 6) * HD;
            base = k + off; oh = kh + off; ol = kl + off; sc2 = 1.0f;
        }
        float x1 = base[d], x2 = base[d + 64];
        float r1 = (x1 * c - x2 * s) * sc2;
        float r2 = (x2 * c + x1 * s) * sc2;
        __nv_bfloat16 h1 = __float2bfloat16(r1);
        __nv_bfloat16 h2 = __float2bfloat16(r2);
        oh[d]      = h1;  ol[d]      = __float2bfloat16(r1 - __bfloat162float(h1));
        oh[d + 64] = h2;  ol[d + 64] = __float2bfloat16(r2 - __bfloat162float(h2));
    }
}

// ---------------------------------------------------------------------------
// tcgen05 causal flash attention. CTA = 128 q-rows x 1 head, 256 threads.
// All tensor ops use verified patterns only:
//   S = Q'K^T : SS-mode, K-major SW128 (== projection GEMM structure)
//   P -> TMEM via STTM, PV TS-mode (== test_mma.cu structure)
//   V consumed K-major from the pre-transposed V^T [dim][t] buffers.
// Fixed-bias softmax p = exp(s - 8); O normalized by l at the end.
// ---------------------------------------------------------------------------
#define ATT_Q    0
#define ATT_K    65536
#define ATT_V    131072
#define ATT_CTRL 196608
#define ATT_SMEM (ATT_CTRL + 64)

__global__ __launch_bounds__(256) void attn_tc_kernel(
    const __nv_bfloat16* __restrict__ qh, const __nv_bfloat16* __restrict__ ql,
    const __nv_bfloat16* __restrict__ kh, const __nv_bfloat16* __restrict__ kl,
    const __nv_bfloat16* __restrict__ vth, const __nv_bfloat16* __restrict__ vtl,
    __nv_bfloat16* __restrict__ aoh, __nv_bfloat16* __restrict__ aol)
{
    extern __shared__ char sm_raw[];
    const uint32_t sb = s2u(sm_raw);
    const int tid  = threadIdx.x;
    const int wid  = tid >> 5;
    const int lane = tid & 31;
    const int h    = blockIdx.y;
    const int qb   = gridDim.x - 1 - blockIdx.x;   // heavy tiles first
    const int hk   = h >> 2;
    const int q0   = qb * 128;

    const uint32_t mbarS  = sb + ATT_CTRL + 0;
    const uint32_t mbarPV = sb + ATT_CTRL + 8;

    if (wid == 0) { tc_alloc(sb + ATT_CTRL + 16, 512); tc_relinq(); }
    if (tid == 0) { mbar_init(mbarS, 1); mbar_init(mbarPV, 1); }
    __syncthreads();
    uint32_t tmem;
    asm volatile("ld.shared.b32 %0, [%1];" : "=r"(tmem) : "r"(sb + ATT_CTRL + 16));
    const uint32_t TM_S = tmem, TM_O = tmem + 128, TM_PH = tmem + 256,
                   TM_PL = tmem + 320;

    const uint32_t idescS  = (1u << 4) | (1u << 7) | (1u << 10) |
                             (16u << 17) | (8u << 24);   // M128 N128
    const uint32_t idescPV = (1u << 4) | (1u << 7) | (1u << 10) |
                             (8u << 17) | (8u << 24);    // M128 N64 (no TransB)

    const int g   = tid & 7;
    const int rb  = tid >> 3;               // 0..31
    const int sub = wid & 3;                // TMEM subpartition
    const int cgp = wid >> 2;               // column group
    const int rloc = sub * 32 + lane;       // q row within tile

    // ---- Q tile (persistent), cp.async group 1: {QH c0, QH c1, QL c0, QL c1}
    {
        const size_t qrow4 = ((size_t)q0 * INNER + h * HD) >> 3;
#pragma unroll
        for (int st = 0; st < 4; st++) {
            const uint4* sp = (const uint4*)((st < 2) ? qh : ql);
            const int c = st & 1;
#pragma unroll
            for (int r = 0; r < 4; r++) {
                int row = rb + 32 * r;
                cp16(sb + ATT_Q + st * 16384 + (row * 8 + (g ^ (row & 7))) * 16,
                     sp + qrow4 + (size_t)row * (INNER / 8) + c * 8 + g);
            }
        }
        cp_commit();
    }

    float l_acc = 0.f;
    int parS = 0, parPV = 0;

    for (int kt = 0; kt <= qb; kt++) {
        const int k0 = kt * 128;
        // ---- K tile cp.async (sK free: S-MMA(kt-1) finished before epilogue)
        {
            const size_t krow4 = ((size_t)k0 * KVI + hk * HD) >> 3;
#pragma unroll
            for (int st = 0; st < 4; st++) {
                const uint4* sp = (const uint4*)((st < 2) ? kh : kl);
                const int c = st & 1;
#pragma unroll
                for (int r = 0; r < 4; r++) {
                    int row = rb + 32 * r;
                    cp16(sb + ATT_K + st * 16384 + (row * 8 + (g ^ (row & 7))) * 16,
                         sp + krow4 + (size_t)row * (KVI / 8) + c * 8 + g);
                }
            }
            cp_commit();
        }
        // ---- PV(kt-1) must finish before sV overwrite / P TMEM overwrite
        if (kt > 0) { mbar_wait(mbarPV, parPV); parPV ^= 1; }
        // ---- V^T tile cp.async: 8 subtiles [64 dims][64 keys] K-major
        {
#pragma unroll
            for (int st = 0; st < 8; st++) {
                const int hl = st >> 2, hf = (st >> 1) & 1, c = st & 1;
                const uint4* sp = (const uint4*)(hl ? vtl : vth);
                const size_t base4 =
                    (((size_t)(hk * 128 + hf * 64)) * T_LEN + k0 + c * 64) >> 3;
#pragma unroll
                for (int r = 0; r < 2; r++) {
                    int row = rb + 32 * r;
                    cp16(sb + ATT_V + st * 8192 + (row * 8 + (g ^ (row & 7))) * 16,
                         sp + base4 + (size_t)row * (T_LEN / 8) + g);
                }
            }
            cp_commit();
        }
        cp_wait1();                 // Q (first iter) + K complete; V may fly
        __syncthreads();
        // ---- S = Q' K^T (3 bf16 passes, SS K-major)
        if (wid == 0 && elect1()) {
            fence_async();
            tc_fence_after();
            uint64_t dQ[4], dK[4];
#pragma unroll
            for (int st = 0; st < 4; st++) {
                dQ[st] = mk_desc(sb + ATT_Q + st * 16384);
                dK[st] = mk_desc(sb + ATT_K + st * 16384);
            }
#pragma unroll
            for (int p = 0; p < 3; p++) {
                const int ai = (p < 2) ? 0 : 2;
                const int bi = (p == 1) ? 2 : 0;
#pragma unroll
                for (int c = 0; c < 2; c++)
#pragma unroll
                    for (int ks = 0; ks < 4; ks++)
                        tc_mma_f16_ss(TM_S, dQ[ai + c] + ks * 2, dK[bi + c] + ks * 2,
                                      idescS, (p == 0 && c == 0 && ks == 0) ? 0u : 1u);
            }
            tc_commit(mbarS);
        }
        // ---- wait S, softmax epilogue (8 warps, 2 col-chunks each)
        mbar_wait(mbarS, parS); parS ^= 1;
        tc_fence_after();
#pragma unroll
        for (int cc = 0; cc < 2; cc++) {
            const int cb = cgp * 2 + cc;
            uint32_t sr[32];
            tc_ld32(sr, TM_S + cb * 32);
            tc_waitld();
            float pr[32];
#pragma unroll
            for (int j = 0; j < 32; j++) {
                float s = __uint_as_float(sr[j]);
                int key = k0 + cb * 32 + j;
                float p = __expf(s - 8.0f);
                if (kt == qb && key > q0 + rloc) p = 0.f;
                pr[j] = p;
                l_acc += p;
            }
            uint32_t ph[16], pl[16];
#pragma unroll
            for (int m = 0; m < 16; m++) {
                float f0 = pr[2 * m], f1 = pr[2 * m + 1];
                __nv_bfloat16 h0 = __float2bfloat16(f0);
                __nv_bfloat16 h1 = __float2bfloat16(f1);
                __nv_bfloat16 l0 = __float2bfloat16(f0 - __bfloat162float(h0));
                __nv_bfloat16 l1 = __float2bfloat16(f1 - __bfloat162float(h1));
                ph[m] = pk2(h0, h1);
                pl[m] = pk2(l0, l1);
            }
            tc_st16(TM_PH + cb * 16 + ((uint32_t)sub << 21), ph);
            tc_st16(TM_PL + cb * 16 + ((uint32_t)sub << 21), pl);
        }
        tc_waitst();
        tc_fence_before();
        cp_wait0();                  // V tiles complete
        __syncthreads();             // P in TMEM + V in smem visible
        // ---- O += P V (TS-mode, K-major V^T subtiles)
        if (wid == 0 && elect1()) {
            fence_async();
            tc_fence_after();
            uint64_t dV[8];
#pragma unroll
            for (int st = 0; st < 8; st++)
                dV[st] = mk_desc(sb + ATT_V + st * 8192);
#pragma unroll
            for (int hf = 0; hf < 2; hf++) {
                const uint32_t D = TM_O + hf * 64;
#pragma unroll
                for (int p = 0; p < 3; p++) {
                    const uint32_t A = (p == 2) ? TM_PL : TM_PH;
                    const int hl = (p == 1) ? 1 : 0;
#pragma unroll
                    for (int c = 0; c < 2; c++)
#pragma unroll
                        for (int ks = 0; ks < 4; ks++)
                            tc_mma_f16_ts(D, A + 32 * c + ks * 8,
                                          dV[(hl * 2 + hf) * 2 + c] + ks * 2,
                                          idescPV,
                                          (kt == 0 && p == 0 && c == 0 && ks == 0)
                                              ? 0u : 1u);
                }
            }
            tc_commit(mbarPV);
        }
    }

    mbar_wait(mbarPV, parPV);
    tc_fence_after();

    // combine l across the two warp-groups (sK area is free)
    float* lbuf = (float*)(sm_raw + ATT_K);
    lbuf[cgp * 128 + rloc] = l_acc;
    __syncthreads();
    const float linv = 1.f / (lbuf[rloc] + lbuf[128 + rloc]);

    // O epilogue: normalize + bf16 hi/lo split
#pragma unroll
    for (int cc = 0; cc < 2; cc++) {
        const int cb = cgp * 2 + cc;
        uint32_t orr[32];
        tc_ld32(orr, TM_O + cb * 32);
        tc_waitld();
        uint32_t hv[16], lv[16];
#pragma unroll
        for (int m = 0; m < 16; m++) {
            float f0 = __uint_as_float(orr[2 * m]) * linv;
            float f1 = __uint_as_float(orr[2 * m + 1]) * linv;
            __nv_bfloat16 h0 = __float2bfloat16(f0);
            __nv_bfloat16 h1 = __float2bfloat16(f1);
            __nv_bfloat16 l0 = __float2bfloat16(f0 - __bfloat162float(h0));
            __nv_bfloat16 l1 = __float2bfloat16(f1 - __bfloat162float(h1));
            hv[m] = pk2(h0, h1);
            lv[m] = pk2(l0, l1);
        }
        uint4* hq = (uint4*)(aoh + (size_t)(q0 + rloc) * INNER + h * HD + cb * 32);
        uint4* lq = (uint4*)(aol + (size_t)(q0 + rloc) * INNER + h * HD + cb * 32);
#pragma unroll
        for (int m = 0; m < 4; m++) {
            hq[m] = *(uint4*)&hv[4 * m];
            lq[m] = *(uint4*)&lv[4 * m];
        }
    }
    tc_fence_before();
    __syncthreads();
    if (wid == 0) tc_dealloc(tmem, 512);
}

// ---------------------------------------------------------------------------
extern "C" void kernel_launch(void* const* d_in, const int* in_sizes, int n_in,
                              void* d_out, int out_size)
{
    (void)in_sizes; (void)n_in; (void)out_size;
    const float* stm = (const float*)d_in[0];
    const float* w_q = (const float*)d_in[1];
    const float* w_k = (const float*)d_in[2];
    const float* w_v = (const float*)d_in[3];
    const float* w_o = (const float*)d_in[4];
    float* out = (float*)d_out;

    float *pq, *pk;
    cudaGetSymbolAddress((void**)&pq, g_q);
    cudaGetSymbolAddress((void**)&pk, g_k);

    __nv_bfloat16 *xh, *xl, *wqh, *wql, *wkh, *wkl, *wvh, *wvl, *woh, *wol;
    __nv_bfloat16 *qhp, *qlp, *khp, *klp, *vth, *vtl, *aoh, *aol;
    cudaGetSymbolAddress((void**)&xh,  g_xh);  cudaGetSymbolAddress((void**)&xl,  g_xl);
    cudaGetSymbolAddress((void**)&wqh, g_wqh); cudaGetSymbolAddress((void**)&wql, g_wql);
    cudaGetSymbolAddress((void**)&wkh, g_wkh); cudaGetSymbolAddress((void**)&wkl, g_wkl);
    cudaGetSymbolAddress((void**)&wvh, g_wvh); cudaGetSymbolAddress((void**)&wvl, g_wvl);
    cudaGetSymbolAddress((void**)&woh, g_woh); cudaGetSymbolAddress((void**)&wol, g_wol);
    cudaGetSymbolAddress((void**)&qhp, g_qh);  cudaGetSymbolAddress((void**)&qlp, g_ql);
    cudaGetSymbolAddress((void**)&khp, g_kh);  cudaGetSymbolAddress((void**)&klp, g_kl);
    cudaGetSymbolAddress((void**)&vth, g_vth); cudaGetSymbolAddress((void**)&vtl, g_vtl);
    cudaGetSymbolAddress((void**)&aoh, g_aoh); cudaGetSymbolAddress((void**)&aol, g_aol);

    cudaFuncSetAttribute(gemm_tc_kernel<0>,
                         cudaFuncAttributeMaxDynamicSharedMemorySize, GSMEM);
    cudaFuncSetAttribute(gemm_tc_kernel<2>,
                         cudaFuncAttributeMaxDynamicSharedMemorySize, GSMEM);
    cudaFuncSetAttribute(attn_tc_kernel,
                         cudaFuncAttributeMaxDynamicSharedMemorySize, ATT_SMEM);

    split_kernel<<<4096, 256>>>(stm, xh,  xl,  T_LEN * INNER);
    split_kernel<<<4096, 256>>>(w_q, wqh, wql, INNER * INNER);
    split_kernel<<<4096, 256>>>(w_k, wkh, wkl, KVI * INNER);
    split_kernel<<<4096, 256>>>(w_v, wvh, wvl, KVI * INNER);
    split_kernel<<<4096, 256>>>(w_o, woh, wol, INNER * INNER);

    gemm_tc_kernel<0><<<dim3(INNER / 128, T_LEN / 128), 256, GSMEM>>>(
        xh, xl, wqh, wql, pq, nullptr, nullptr, INNER, INNER);
    gemm_tc_kernel<0><<<dim3(KVI / 128, T_LEN / 128), 256, GSMEM>>>(
        xh, xl, wkh, wkl, pk, nullptr, nullptr, KVI, INNER);
    gemm_tc_kernel<2><<<dim3(KVI / 128, T_LEN / 128), 256, GSMEM>>>(
        xh, xl, wvh, wvl, nullptr, vth, vtl, KVI, INNER);

    rope_kernel<<<T_LEN, 256>>>(pq, pk, qhp, qlp, khp, klp);

    attn_tc_kernel<<<dim3(T_LEN / 128, NH), 256, ATT_SMEM>>>(
        qhp, qlp, khp, klp, vth, vtl, aoh, aol);

    gemm_tc_kernel<0><<<dim3(INNER / 128, T_LEN / 128), 256, GSMEM>>>(
        aoh, aol, woh, wol, out, nullptr, nullptr, INNER, INNER);
}